// round 2
// baseline (speedup 1.0000x reference)
#include <cuda_runtime.h>
#include <cuda_bf16.h>

#define Bc 2
#define Nc 1000
#define Ec 2000
#define Hc 128

// Scratch (no allocations allowed): permuted edge_network, n2e embedding, new edge states
__device__ float g_ENp[Hc * Hc * Hc];   // [i][h][j]  8.4 MB
__device__ float g_emb[Bc * Ec * Hc];   // [b][e][j]  2 MB
__device__ float g_new[Bc * Ec * Hc];   // [b][e][i]  2 MB

// ---------------------------------------------------------------------------
// Stage 1: permute EN[h][i][j] -> ENp[i][h][j]
// ---------------------------------------------------------------------------
__global__ void k_permute(const float* __restrict__ EN) {
    int j = threadIdx.x;
    int i = blockIdx.x, h = blockIdx.y;
    g_ENp[(i * Hc + h) * Hc + j] = EN[(h * Hc + i) * Hc + j];
}

// ---------------------------------------------------------------------------
// Stage 2: emb[b][e][h] = sum_n node2edge[b][e][n] * node_state[b][n][h]
// Tile: 128 e-rows x 128 h-cols (all of H), KT=8 over N=1000 (125 iters).
// A is K-contiguous -> transpose-on-store into As[kk][row] (+1 pad).
// ---------------------------------------------------------------------------
__global__ __launch_bounds__(256) void k_gemm_n2e(const float* __restrict__ n2e,
                                                  const float* __restrict__ ns) {
    const int b  = blockIdx.y;
    const int e0 = blockIdx.x * 128;
    const float* A  = n2e + (long)b * Ec * Nc;   // [e][n]
    const float* Bm = ns  + (long)b * Nc * Hc;   // [n][h]
    __shared__ float As[8][129];
    __shared__ float Bs[8][128];

    const int tid = threadIdx.x;
    const int tx = tid & 15, ty = tid >> 4;
    const int lr = tid >> 1;          // row this thread loads for A
    const int lk = (tid & 1) * 4;     // k-offset (float4)

    float acc[8][8];
#pragma unroll
    for (int r = 0; r < 8; r++)
#pragma unroll
        for (int c = 0; c < 8; c++) acc[r][c] = 0.f;

    for (int k0 = 0; k0 < Nc; k0 += 8) {
        float4 av = make_float4(0.f, 0.f, 0.f, 0.f);
        if (e0 + lr < Ec)
            av = *reinterpret_cast<const float4*>(&A[(long)(e0 + lr) * Nc + k0 + lk]);
        As[lk + 0][lr] = av.x; As[lk + 1][lr] = av.y;
        As[lk + 2][lr] = av.z; As[lk + 3][lr] = av.w;

        const int bk = tid >> 5;          // 0..7
        const int bc = (tid & 31) * 4;    // 0..124
        float4 bv = *reinterpret_cast<const float4*>(&Bm[(long)(k0 + bk) * Hc + bc]);
        *reinterpret_cast<float4*>(&Bs[bk][bc]) = bv;
        __syncthreads();

#pragma unroll
        for (int kk = 0; kk < 8; kk++) {
            float a[8], bb[8];
#pragma unroll
            for (int r = 0; r < 8; r++) a[r]  = As[kk][ty + r * 16];
#pragma unroll
            for (int c = 0; c < 8; c++) bb[c] = Bs[kk][tx + c * 16];
#pragma unroll
            for (int r = 0; r < 8; r++)
#pragma unroll
                for (int c = 0; c < 8; c++) acc[r][c] += a[r] * bb[c];
        }
        __syncthreads();
    }

    float* C = g_emb + (long)b * Ec * Hc;
#pragma unroll
    for (int r = 0; r < 8; r++) {
        int e = e0 + ty + r * 16;
        if (e < Ec) {
#pragma unroll
            for (int c = 0; c < 8; c++) C[(long)e * Hc + tx + c * 16] = acc[r][c];
        }
    }
}

// ---------------------------------------------------------------------------
// Stage 3: new_n2e[b][e][i] = sum_h ev[b][e][h] * (sum_j ENp[i][h][j]*emb[b][e][j])
// Per CTA: fixed (b, i, e-block of 128). GEMM S[h][e] (128x128, K=128) then
// fused ev-weighted reduction over h.
// ---------------------------------------------------------------------------
__global__ __launch_bounds__(256) void k_edgeconv(const float* __restrict__ ev) {
    const int e0 = blockIdx.x * 128;
    const int i  = blockIdx.y;
    const int b  = blockIdx.z;
    const float* A  = g_ENp + (long)i * Hc * Hc;   // [h][j]
    const float* Bm = g_emb + (long)b * Ec * Hc;   // [e][j]

    __shared__ float As[8][129];
    __shared__ float Bs[8][129];
    __shared__ float evs[128][17];
    __shared__ float out_s[128];

    const int tid = threadIdx.x;
    const int tx = tid & 15, ty = tid >> 4;
    const int lr = tid >> 1;
    const int lk = (tid & 1) * 4;

    float acc[8][8];   // [h-frag rr][e-frag cc], h = ty + rr*16, e = tx + cc*16
#pragma unroll
    for (int r = 0; r < 8; r++)
#pragma unroll
        for (int c = 0; c < 8; c++) acc[r][c] = 0.f;

    if (tid < 128) out_s[tid] = 0.f;

    for (int k0 = 0; k0 < Hc; k0 += 8) {
        float4 av = *reinterpret_cast<const float4*>(&A[(long)lr * Hc + k0 + lk]);
        As[lk + 0][lr] = av.x; As[lk + 1][lr] = av.y;
        As[lk + 2][lr] = av.z; As[lk + 3][lr] = av.w;

        float4 bv = make_float4(0.f, 0.f, 0.f, 0.f);
        if (e0 + lr < Ec)
            bv = *reinterpret_cast<const float4*>(&Bm[(long)(e0 + lr) * Hc + k0 + lk]);
        Bs[lk + 0][lr] = bv.x; Bs[lk + 1][lr] = bv.y;
        Bs[lk + 2][lr] = bv.z; Bs[lk + 3][lr] = bv.w;
        __syncthreads();

#pragma unroll
        for (int kk = 0; kk < 8; kk++) {
            float a[8], bb[8];
#pragma unroll
            for (int r = 0; r < 8; r++) a[r]  = As[kk][ty + r * 16];
#pragma unroll
            for (int c = 0; c < 8; c++) bb[c] = Bs[kk][tx + c * 16];
#pragma unroll
            for (int r = 0; r < 8; r++)
#pragma unroll
                for (int c = 0; c < 8; c++) acc[r][c] += a[r] * bb[c];
        }
        __syncthreads();
    }

    // Epilogue: out[e] = sum_h ev[b][e][h] * S[h][e].
    // h chunks of 16 match fragment index rr (h = ty + rr*16).
    float partial[8];
#pragma unroll
    for (int c = 0; c < 8; c++) partial[c] = 0.f;

    for (int ch = 0; ch < 8; ch++) {
        __syncthreads();
        const int ee = tid >> 1;
        const int hh = (tid & 1) * 8;
        float4 v0 = make_float4(0.f, 0.f, 0.f, 0.f), v1 = v0;
        if (e0 + ee < Ec) {
            const float* p = ev + ((long)b * Ec + e0 + ee) * Hc + ch * 16 + hh;
            v0 = *reinterpret_cast<const float4*>(p);
            v1 = *reinterpret_cast<const float4*>(p + 4);
        }
        evs[ee][hh + 0] = v0.x; evs[ee][hh + 1] = v0.y;
        evs[ee][hh + 2] = v0.z; evs[ee][hh + 3] = v0.w;
        evs[ee][hh + 4] = v1.x; evs[ee][hh + 5] = v1.y;
        evs[ee][hh + 6] = v1.z; evs[ee][hh + 7] = v1.w;
        __syncthreads();

#pragma unroll
        for (int c = 0; c < 8; c++)
            partial[c] += evs[tx + c * 16][ty] * acc[ch][c];
    }

#pragma unroll
    for (int c = 0; c < 8; c++) atomicAdd(&out_s[tx + c * 16], partial[c]);
    __syncthreads();

    if (tid < 128 && e0 + tid < Ec)
        g_new[((long)b * Ec + e0 + tid) * Hc + i] = out_s[tid];
}

// ---------------------------------------------------------------------------
// Stage 4: agg[b][n][i] = (sum_e e2n[b][n][e]*g_new[b][e][i] + ns[b][n][i]) / norm
// norm[n] = 1 + row-sum of e2n, fused into A-tile loads (each A element read once).
// ---------------------------------------------------------------------------
__global__ __launch_bounds__(256) void k_agg(const float* __restrict__ e2n,
                                             const float* __restrict__ ns,
                                             float* __restrict__ out) {
    const int b  = blockIdx.y;
    const int n0 = blockIdx.x * 128;
    const float* A  = e2n   + (long)b * Nc * Ec;   // [n][e]
    const float* Bm = g_new + (long)b * Ec * Hc;   // [e][i]

    __shared__ float As[8][129];
    __shared__ float Bs[8][128];
    __shared__ float norm_s[128];

    const int tid = threadIdx.x;
    const int tx = tid & 15, ty = tid >> 4;
    const int lr = tid >> 1;
    const int lk = (tid & 1) * 4;

    float acc[8][8];
#pragma unroll
    for (int r = 0; r < 8; r++)
#pragma unroll
        for (int c = 0; c < 8; c++) acc[r][c] = 0.f;
    float rs = 0.f;

    if (tid < 128) norm_s[tid] = 1.0f;

    for (int k0 = 0; k0 < Ec; k0 += 8) {
        float4 av = make_float4(0.f, 0.f, 0.f, 0.f);
        if (n0 + lr < Nc)
            av = *reinterpret_cast<const float4*>(&A[(long)(n0 + lr) * Ec + k0 + lk]);
        As[lk + 0][lr] = av.x; As[lk + 1][lr] = av.y;
        As[lk + 2][lr] = av.z; As[lk + 3][lr] = av.w;
        rs += av.x + av.y + av.z + av.w;

        const int bk = tid >> 5;
        const int bc = (tid & 31) * 4;
        float4 bv = *reinterpret_cast<const float4*>(&Bm[(long)(k0 + bk) * Hc + bc]);
        *reinterpret_cast<float4*>(&Bs[bk][bc]) = bv;
        __syncthreads();

#pragma unroll
        for (int kk = 0; kk < 8; kk++) {
            float a[8], bb[8];
#pragma unroll
            for (int r = 0; r < 8; r++) a[r]  = As[kk][ty + r * 16];
#pragma unroll
            for (int c = 0; c < 8; c++) bb[c] = Bs[kk][tx + c * 16];
#pragma unroll
            for (int r = 0; r < 8; r++)
#pragma unroll
                for (int c = 0; c < 8; c++) acc[r][c] += a[r] * bb[c];
        }
        __syncthreads();
    }

    atomicAdd(&norm_s[lr], rs);   // two threads per row, each summed half the k's
    __syncthreads();

    const float* NS = ns + (long)b * Nc * Hc;
#pragma unroll
    for (int r = 0; r < 8; r++) {
        int n = n0 + ty + r * 16;
        if (n < Nc) {
            float nm = norm_s[ty + r * 16];
#pragma unroll
            for (int c = 0; c < 8; c++) {
                int h = tx + c * 16;
                out[((long)b * Nc + n) * Hc + h] = (acc[r][c] + NS[(long)n * Hc + h]) / nm;
            }
        }
    }
}

// ---------------------------------------------------------------------------
extern "C" void kernel_launch(void* const* d_in, const int* in_sizes, int n_in,
                              void* d_out, int out_size) {
    const float* node_state   = (const float*)d_in[0];   // [B,N,H]
    const float* edge_vec     = (const float*)d_in[1];   // [B,E,H]
    const float* node2edge    = (const float*)d_in[2];   // [B,E,N]
    const float* edge2node    = (const float*)d_in[3];   // [B,N,E]
    const float* edge_network = (const float*)d_in[4];   // [H,H,H]
    float* out = (float*)d_out;

    dim3 g1(Hc, Hc);
    k_permute<<<g1, Hc>>>(edge_network);

    dim3 g2((Ec + 127) / 128, Bc);
    k_gemm_n2e<<<g2, 256>>>(node2edge, node_state);

    dim3 g3((Ec + 127) / 128, Hc, Bc);
    k_edgeconv<<<g3, 256>>>(edge_vec);

    dim3 g4((Nc + 127) / 128, Bc);
    k_agg<<<g4, 256>>>(edge2node, node_state, out);
}

// round 4
// speedup vs baseline: 1.5831x; 1.5831x over previous
#include <cuda_runtime.h>
#include <cuda_bf16.h>

#define Bc 2
#define Nc 1000
#define Ec 2000
#define Hc 128
#define S2 5     // split-K for stage 2 (N=1000 -> 5 x 200)
#define S4 10    // split-K for stage 4 (E=2000 -> 10 x 200)

// Scratch (no allocations allowed).
// g_part is time-shared: stage-2 partials [S2][B*E*H] then stage-4 partials
// [S4][B*N*H] (same total size: 5*2000 == 10*1000).
__device__ float g_ENp[Hc * Hc * Hc];            // [i][h][j]  8.4 MB
__device__ float g_emb[Bc * Ec * Hc];            // [b][e][j]  2 MB
__device__ float g_new[Bc * Ec * Hc];            // [b][e][i]  2 MB
__device__ float g_part[S2 * Bc * Ec * Hc];      // 10.24 MB shared scratch
__device__ float g_normp[S4][Bc * Nc];           // stage-4 norm partials

// ---------------------------------------------------------------------------
// Stage 1: permute EN[h][i][j] -> ENp[i][h][j]
// ---------------------------------------------------------------------------
__global__ void k_permute(const float* __restrict__ EN) {
    int j = threadIdx.x;
    int i = blockIdx.x, h = blockIdx.y;
    g_ENp[(i * Hc + h) * Hc + j] = EN[(h * Hc + i) * Hc + j];
}

// ---------------------------------------------------------------------------
// Stage 2 (split-K): part[s][b][e][h] = sum_{n in chunk s} n2e[b][e][n]*ns[b][n][h]
// grid (eblk, s, b). chunk = Nc/S2 = 200 (25 k-steps of 8).
// ---------------------------------------------------------------------------
__global__ __launch_bounds__(256) void k_gemm_n2e_part(const float* __restrict__ n2e,
                                                       const float* __restrict__ ns) {
    const int b  = blockIdx.z;
    const int s  = blockIdx.y;
    const int e0 = blockIdx.x * 128;
    const int kbeg = s * (Nc / S2);
    const int kend = kbeg + (Nc / S2);
    const float* A  = n2e + (long)b * Ec * Nc;   // [e][n]
    const float* Bm = ns  + (long)b * Nc * Hc;   // [n][h]
    __shared__ float As[8][129];
    __shared__ float Bs[8][128];

    const int tid = threadIdx.x;
    const int tx = tid & 15, ty = tid >> 4;
    const int lr = tid >> 1;
    const int lk = (tid & 1) * 4;

    float acc[8][8];
#pragma unroll
    for (int r = 0; r < 8; r++)
#pragma unroll
        for (int c = 0; c < 8; c++) acc[r][c] = 0.f;

    for (int k0 = kbeg; k0 < kend; k0 += 8) {
        float4 av = make_float4(0.f, 0.f, 0.f, 0.f);
        if (e0 + lr < Ec)
            av = *reinterpret_cast<const float4*>(&A[(long)(e0 + lr) * Nc + k0 + lk]);
        As[lk + 0][lr] = av.x; As[lk + 1][lr] = av.y;
        As[lk + 2][lr] = av.z; As[lk + 3][lr] = av.w;

        const int bk = tid >> 5;
        const int bc = (tid & 31) * 4;
        float4 bv = *reinterpret_cast<const float4*>(&Bm[(long)(k0 + bk) * Hc + bc]);
        *reinterpret_cast<float4*>(&Bs[bk][bc]) = bv;
        __syncthreads();

#pragma unroll
        for (int kk = 0; kk < 8; kk++) {
            float a[8], bb[8];
#pragma unroll
            for (int r = 0; r < 8; r++) a[r]  = As[kk][ty + r * 16];
#pragma unroll
            for (int c = 0; c < 8; c++) bb[c] = Bs[kk][tx + c * 16];
#pragma unroll
            for (int r = 0; r < 8; r++)
#pragma unroll
                for (int c = 0; c < 8; c++) acc[r][c] += a[r] * bb[c];
        }
        __syncthreads();
    }

    float* C = g_part + ((long)s * Bc + b) * Ec * Hc;
#pragma unroll
    for (int r = 0; r < 8; r++) {
        int e = e0 + ty + r * 16;
        if (e < Ec) {
#pragma unroll
            for (int c = 0; c < 8; c++) C[(long)e * Hc + tx + c * 16] = acc[r][c];
        }
    }
}

// Reduce stage-2 partials into g_emb (float4, deterministic)
__global__ __launch_bounds__(256) void k_reduce_emb() {
    int idx = blockIdx.x * blockDim.x + threadIdx.x;
    const int total = Bc * Ec * Hc / 4;
    if (idx >= total) return;
    float4 a = reinterpret_cast<const float4*>(g_part)[idx];
#pragma unroll
    for (int s = 1; s < S2; s++) {
        float4 v = reinterpret_cast<const float4*>(g_part + (long)s * Bc * Ec * Hc)[idx];
        a.x += v.x; a.y += v.y; a.z += v.z; a.w += v.w;
    }
    reinterpret_cast<float4*>(g_emb)[idx] = a;
}

// ---------------------------------------------------------------------------
// Stage 3: new_n2e[b][e][i] = sum_h ev[b][e][h] * (sum_j ENp[i][h][j]*emb[b][e][j])
// ---------------------------------------------------------------------------
__global__ __launch_bounds__(256) void k_edgeconv(const float* __restrict__ ev) {
    const int e0 = blockIdx.x * 128;
    const int i  = blockIdx.y;
    const int b  = blockIdx.z;
    const float* A  = g_ENp + (long)i * Hc * Hc;   // [h][j]
    const float* Bm = g_emb + (long)b * Ec * Hc;   // [e][j]

    __shared__ float As[8][129];
    __shared__ float Bs[8][129];
    __shared__ float evs[128][17];
    __shared__ float out_s[128];

    const int tid = threadIdx.x;
    const int tx = tid & 15, ty = tid >> 4;
    const int lr = tid >> 1;
    const int lk = (tid & 1) * 4;

    float acc[8][8];
#pragma unroll
    for (int r = 0; r < 8; r++)
#pragma unroll
        for (int c = 0; c < 8; c++) acc[r][c] = 0.f;

    if (tid < 128) out_s[tid] = 0.f;

    for (int k0 = 0; k0 < Hc; k0 += 8) {
        float4 av = *reinterpret_cast<const float4*>(&A[(long)lr * Hc + k0 + lk]);
        As[lk + 0][lr] = av.x; As[lk + 1][lr] = av.y;
        As[lk + 2][lr] = av.z; As[lk + 3][lr] = av.w;

        float4 bv = make_float4(0.f, 0.f, 0.f, 0.f);
        if (e0 + lr < Ec)
            bv = *reinterpret_cast<const float4*>(&Bm[(long)(e0 + lr) * Hc + k0 + lk]);
        Bs[lk + 0][lr] = bv.x; Bs[lk + 1][lr] = bv.y;
        Bs[lk + 2][lr] = bv.z; Bs[lk + 3][lr] = bv.w;
        __syncthreads();

#pragma unroll
        for (int kk = 0; kk < 8; kk++) {
            float a[8], bb[8];
#pragma unroll
            for (int r = 0; r < 8; r++) a[r]  = As[kk][ty + r * 16];
#pragma unroll
            for (int c = 0; c < 8; c++) bb[c] = Bs[kk][tx + c * 16];
#pragma unroll
            for (int r = 0; r < 8; r++)
#pragma unroll
                for (int c = 0; c < 8; c++) acc[r][c] += a[r] * bb[c];
        }
        __syncthreads();
    }

    float partial[8];
#pragma unroll
    for (int c = 0; c < 8; c++) partial[c] = 0.f;

    for (int ch = 0; ch < 8; ch++) {
        __syncthreads();
        const int ee = tid >> 1;
        const int hh = (tid & 1) * 8;
        float4 v0 = make_float4(0.f, 0.f, 0.f, 0.f), v1 = v0;
        if (e0 + ee < Ec) {
            const float* p = ev + ((long)b * Ec + e0 + ee) * Hc + ch * 16 + hh;
            v0 = *reinterpret_cast<const float4*>(p);
            v1 = *reinterpret_cast<const float4*>(p + 4);
        }
        evs[ee][hh + 0] = v0.x; evs[ee][hh + 1] = v0.y;
        evs[ee][hh + 2] = v0.z; evs[ee][hh + 3] = v0.w;
        evs[ee][hh + 4] = v1.x; evs[ee][hh + 5] = v1.y;
        evs[ee][hh + 6] = v1.z; evs[ee][hh + 7] = v1.w;
        __syncthreads();

#pragma unroll
        for (int c = 0; c < 8; c++)
            partial[c] += evs[tx + c * 16][ty] * acc[ch][c];
    }

#pragma unroll
    for (int c = 0; c < 8; c++) atomicAdd(&out_s[tx + c * 16], partial[c]);
    __syncthreads();

    if (tid < 128 && e0 + tid < Ec)
        g_new[((long)b * Ec + e0 + tid) * Hc + i] = out_s[tid];
}

// ---------------------------------------------------------------------------
// Stage 4 (split-K): part[s][b][n][i] = sum_{e in chunk s} e2n[b][n][e]*g_new[b][e][i]
// normp[s][b][n] = row-sum of chunk. grid (nblk, s, b). chunk = Ec/S4 = 200.
// ---------------------------------------------------------------------------
__global__ __launch_bounds__(256) void k_agg_part(const float* __restrict__ e2n) {
    const int b  = blockIdx.z;
    const int s  = blockIdx.y;
    const int n0 = blockIdx.x * 128;
    const int kbeg = s * (Ec / S4);
    const int kend = kbeg + (Ec / S4);
    const float* A  = e2n   + (long)b * Nc * Ec;   // [n][e]
    const float* Bm = g_new + (long)b * Ec * Hc;   // [e][i]

    __shared__ float As[8][129];
    __shared__ float Bs[8][128];
    __shared__ float rs2[128][2];

    const int tid = threadIdx.x;
    const int tx = tid & 15, ty = tid >> 4;
    const int lr = tid >> 1;
    const int half = tid & 1;
    const int lk = half * 4;

    float acc[8][8];
#pragma unroll
    for (int r = 0; r < 8; r++)
#pragma unroll
        for (int c = 0; c < 8; c++) acc[r][c] = 0.f;
    float rs = 0.f;

    for (int k0 = kbeg; k0 < kend; k0 += 8) {
        float4 av = make_float4(0.f, 0.f, 0.f, 0.f);
        if (n0 + lr < Nc)
            av = *reinterpret_cast<const float4*>(&A[(long)(n0 + lr) * Ec + k0 + lk]);
        As[lk + 0][lr] = av.x; As[lk + 1][lr] = av.y;
        As[lk + 2][lr] = av.z; As[lk + 3][lr] = av.w;
        rs += av.x + av.y + av.z + av.w;

        const int bk = tid >> 5;
        const int bc = (tid & 31) * 4;
        float4 bv = *reinterpret_cast<const float4*>(&Bm[(long)(k0 + bk) * Hc + bc]);
        *reinterpret_cast<float4*>(&Bs[bk][bc]) = bv;
        __syncthreads();

#pragma unroll
        for (int kk = 0; kk < 8; kk++) {
            float a[8], bb[8];
#pragma unroll
            for (int r = 0; r < 8; r++) a[r]  = As[kk][ty + r * 16];
#pragma unroll
            for (int c = 0; c < 8; c++) bb[c] = Bs[kk][tx + c * 16];
#pragma unroll
            for (int r = 0; r < 8; r++)
#pragma unroll
                for (int c = 0; c < 8; c++) acc[r][c] += a[r] * bb[c];
        }
        __syncthreads();
    }

    rs2[lr][half] = rs;
    __syncthreads();
    if (tid < 128 && n0 + tid < Nc)
        g_normp[s][(long)b * Nc + n0 + tid] = rs2[tid][0] + rs2[tid][1];

    float* C = g_part + ((long)s * Bc + b) * Nc * Hc;
#pragma unroll
    for (int r = 0; r < 8; r++) {
        int n = n0 + ty + r * 16;
        if (n < Nc) {
#pragma unroll
            for (int c = 0; c < 8; c++) C[(long)n * Hc + tx + c * 16] = acc[r][c];
        }
    }
}

// Final reduce: out[b][n][h] = (sum_s part + ns) / (1 + sum_s normp)
__global__ __launch_bounds__(256) void k_reduce_agg(const float* __restrict__ ns,
                                                    float* __restrict__ out) {
    int idx = blockIdx.x * blockDim.x + threadIdx.x;   // float4 index
    const int total = Bc * Nc * Hc / 4;
    if (idx >= total) return;
    const int row = (idx * 4) / Hc;       // b*Nc + n
    float nm = 1.0f;
#pragma unroll
    for (int s = 0; s < S4; s++) nm += g_normp[s][row];

    float4 a = reinterpret_cast<const float4*>(g_part)[idx];
#pragma unroll
    for (int s = 1; s < S4; s++) {
        float4 v = reinterpret_cast<const float4*>(g_part + (long)s * Bc * Nc * Hc)[idx];
        a.x += v.x; a.y += v.y; a.z += v.z; a.w += v.w;
    }
    float4 nv = reinterpret_cast<const float4*>(ns)[idx];
    float inv = 1.0f / nm;
    a.x = (a.x + nv.x) * inv; a.y = (a.y + nv.y) * inv;
    a.z = (a.z + nv.z) * inv; a.w = (a.w + nv.w) * inv;
    reinterpret_cast<float4*>(out)[idx] = a;
}

// ---------------------------------------------------------------------------
extern "C" void kernel_launch(void* const* d_in, const int* in_sizes, int n_in,
                              void* d_out, int out_size) {
    const float* node_state   = (const float*)d_in[0];   // [B,N,H]
    const float* edge_vec     = (const float*)d_in[1];   // [B,E,H]
    const float* node2edge    = (const float*)d_in[2];   // [B,E,N]
    const float* edge2node    = (const float*)d_in[3];   // [B,N,E]
    const float* edge_network = (const float*)d_in[4];   // [H,H,H]
    float* out = (float*)d_out;

    dim3 g1(Hc, Hc);
    k_permute<<<g1, Hc>>>(edge_network);

    dim3 g2((Ec + 127) / 128, S2, Bc);
    k_gemm_n2e_part<<<g2, 256>>>(node2edge, node_state);

    int tot2 = Bc * Ec * Hc / 4;
    k_reduce_emb<<<(tot2 + 255) / 256, 256>>>();

    dim3 g3((Ec + 127) / 128, Hc, Bc);
    k_edgeconv<<<g3, 256>>>(edge_vec);

    dim3 g4((Nc + 127) / 128, S4, Bc);
    k_agg_part<<<g4, 256>>>(edge2node);

    int tot4 = Bc * Nc * Hc / 4;
    k_reduce_agg<<<(tot4 + 255) / 256, 256>>>(node_state, out);
}

// round 11
// speedup vs baseline: 2.7458x; 1.7344x over previous
#include <cuda_runtime.h>
#include <cuda_bf16.h>
#include <cstdint>

#define Bc 2
#define Nc 1000
#define Ec 2000
#define Hc 128
#define S2 5      // split-K for stage 2 (N=1000 -> 5 x 200)
#define S4 10     // split-K for stage 4 (E=2000 -> 10 x 200)
#define HCH 4     // stage-3 h-chunks (4 x 32)

#define ENPITCH 144                    // bf16 elems per padded row (288 B)
#define ENTILE_B (128 * ENPITCH * 2)   // 36864 B per h tile

// ---------------------------------------------------------------------------
// Scratch (no allocations). g_part time-shared across disjoint stage lifetimes.
// ---------------------------------------------------------------------------
__device__ float         g_emb [Bc * Ec * Hc];
__device__ float         g_new [Bc * Ec * Hc];
__device__ float         g_part[S2 * Bc * Ec * Hc];       // 10.24 MB
__device__ float         g_normp[S4][Bc * Nc];
__device__ __nv_bfloat16 g_ENhi[128 * 128 * ENPITCH];     // [h][i][j] padded, 4.7 MB
__device__ __nv_bfloat16 g_ENlo[128 * 128 * ENPITCH];

// ---------------------------------------------------------------------------
// PTX helpers (sm_80-era: valid for plain sm_103 target)
// ---------------------------------------------------------------------------
#define CP16(dst, src) \
    asm volatile("cp.async.cg.shared.global [%0], [%1], 16;" :: "r"(dst), "l"(src))
#define CP_COMMIT() asm volatile("cp.async.commit_group;")
#define CP_WAIT0()  asm volatile("cp.async.wait_group 0;" ::: "memory")

#define LDSM_X4(r, addr) \
    asm volatile("ldmatrix.sync.aligned.m8n8.x4.shared.b16 {%0,%1,%2,%3}, [%4];" \
                 : "=r"((r)[0]), "=r"((r)[1]), "=r"((r)[2]), "=r"((r)[3]) : "r"(addr))

#define MMA16816(d, a, b) \
    asm volatile("mma.sync.aligned.m16n8k16.row.col.f32.bf16.bf16.f32 " \
                 "{%0,%1,%2,%3}, {%4,%5,%6,%7}, {%8,%9}, {%0,%1,%2,%3};" \
                 : "+f"((d)[0]), "+f"((d)[1]), "+f"((d)[2]), "+f"((d)[3]) \
                 : "r"((a)[0]), "r"((a)[1]), "r"((a)[2]), "r"((a)[3]), \
                   "r"((b)[0]), "r"((b)[1]))

// SMEM layout for stage-3 kernel (221184 B total)
#define OFF_ZHI   0
#define OFF_ZLO   36864
#define OFF_ENH0  73728
#define OFF_ENL0  110592
#define OFF_ENH1  147456
#define OFF_ENL1  184320
#define SMEM3_TOTAL 221184

// ---------------------------------------------------------------------------
// Stage 1: split EN[h][i][j] fp32 -> bf16 hi/lo padded row-major per-h tiles
// ---------------------------------------------------------------------------
__global__ void k_split_en(const float* __restrict__ EN) {
    int j = threadIdx.x, h = blockIdx.x, i = blockIdx.y;
    float x = EN[((long)h * Hc + i) * Hc + j];
    __nv_bfloat16 hi = __float2bfloat16(x);
    __nv_bfloat16 lo = __float2bfloat16(x - __bfloat162float(hi));
    long off = ((long)h * 128 + i) * ENPITCH + j;
    g_ENhi[off] = hi;
    g_ENlo[off] = lo;
}

// ---------------------------------------------------------------------------
// Stage 2 (split-K, fp32 FFMA)
// ---------------------------------------------------------------------------
__global__ __launch_bounds__(256) void k_gemm_n2e_part(const float* __restrict__ n2e,
                                                       const float* __restrict__ ns) {
    const int b  = blockIdx.z;
    const int s  = blockIdx.y;
    const int e0 = blockIdx.x * 128;
    const int kbeg = s * (Nc / S2);
    const int kend = kbeg + (Nc / S2);
    const float* A  = n2e + (long)b * Ec * Nc;
    const float* Bm = ns  + (long)b * Nc * Hc;
    __shared__ float As[8][129];
    __shared__ float Bs[8][128];

    const int tid = threadIdx.x;
    const int tx = tid & 15, ty = tid >> 4;
    const int lr = tid >> 1;
    const int lk = (tid & 1) * 4;

    float acc[8][8];
#pragma unroll
    for (int r = 0; r < 8; r++)
#pragma unroll
        for (int c = 0; c < 8; c++) acc[r][c] = 0.f;

    for (int k0 = kbeg; k0 < kend; k0 += 8) {
        float4 av = make_float4(0.f, 0.f, 0.f, 0.f);
        if (e0 + lr < Ec)
            av = *reinterpret_cast<const float4*>(&A[(long)(e0 + lr) * Nc + k0 + lk]);
        As[lk + 0][lr] = av.x; As[lk + 1][lr] = av.y;
        As[lk + 2][lr] = av.z; As[lk + 3][lr] = av.w;

        const int bk = tid >> 5;
        const int bc = (tid & 31) * 4;
        float4 bv = *reinterpret_cast<const float4*>(&Bm[(long)(k0 + bk) * Hc + bc]);
        *reinterpret_cast<float4*>(&Bs[bk][bc]) = bv;
        __syncthreads();

#pragma unroll
        for (int kk = 0; kk < 8; kk++) {
            float a[8], bb[8];
#pragma unroll
            for (int r = 0; r < 8; r++) a[r]  = As[kk][ty + r * 16];
#pragma unroll
            for (int c = 0; c < 8; c++) bb[c] = Bs[kk][tx + c * 16];
#pragma unroll
            for (int r = 0; r < 8; r++)
#pragma unroll
                for (int c = 0; c < 8; c++) acc[r][c] += a[r] * bb[c];
        }
        __syncthreads();
    }

    float* C = g_part + ((long)s * Bc + b) * Ec * Hc;
#pragma unroll
    for (int r = 0; r < 8; r++) {
        int e = e0 + ty + r * 16;
        if (e < Ec) {
#pragma unroll
            for (int c = 0; c < 8; c++) C[(long)e * Hc + tx + c * 16] = acc[r][c];
        }
    }
}

__global__ __launch_bounds__(256) void k_reduce_emb() {
    int idx = blockIdx.x * blockDim.x + threadIdx.x;
    const int total = Bc * Ec * Hc / 4;
    if (idx >= total) return;
    float4 a = reinterpret_cast<const float4*>(g_part)[idx];
#pragma unroll
    for (int s = 1; s < S2; s++) {
        float4 v = reinterpret_cast<const float4*>(g_part + (long)s * Bc * Ec * Hc)[idx];
        a.x += v.x; a.y += v.y; a.z += v.z; a.w += v.w;
    }
    reinterpret_cast<float4*>(g_emb)[idx] = a;
}

// ---------------------------------------------------------------------------
// Stage 3 (mma.sync bf16x3): per CTA (eblk, hchunk, b):
//   for h in chunk: Z_h[e,j]=ev[e,h]*emb[e,j] (bf16 hi/lo in smem);
//   D[e,i] += Zhi*ENhi + Zhi*ENlo + Zlo*ENhi   (fp32 register fragments)
// EN tile is [i][j] row-major (i = output col, j = K); for mma.row.col the
// B fragment lane l needs EN[n=l/4][k=2(l%4)+{0,1}] -> NON-trans ldmatrix.
// ---------------------------------------------------------------------------
__global__ __launch_bounds__(256, 1)
void k_edgeconv_mma(const float* __restrict__ ev) {
    extern __shared__ char smem[];
    const uint32_t sb = (uint32_t)__cvta_generic_to_shared(smem);
    const int e0 = blockIdx.x * 128;
    const int hb = blockIdx.y * 32;
    const int b  = blockIdx.z;
    const int tid = threadIdx.x;
    const int lane = tid & 31, wid = tid >> 5;
    const int wm = wid & 3, wn = wid >> 2;   // warp tile: rows wm*32, cols wn*64

    // ldmatrix per-lane base offsets (bytes within a tile)
    // A (row-major 16x16 from Z): row = wm*32 + lane%16 (+mt*16), col half = lane/16
    const uint32_t aoff = (uint32_t)(wm * 32 + (lane & 15)) * 288u + (uint32_t)(lane >> 4) * 16u;
    // B (non-trans, EN [n][k]): x4 matrices (n-blk, k-blk):
    //   lanes 0-7:(n0-7,k0-7) 8-15:(n0-7,k8-15) 16-23:(n8-15,k0-7) 24-31:(n8-15,k8-15)
    const uint32_t boff = (uint32_t)(wn * 64 + (lane & 7) + ((lane >> 4) & 1) * 8) * 288u
                        + (uint32_t)((lane >> 3) & 1) * 16u;

    float d[2][8][4];
#pragma unroll
    for (int mt = 0; mt < 2; mt++)
#pragma unroll
        for (int nt = 0; nt < 8; nt++)
#pragma unroll
            for (int q = 0; q < 4; q++) d[mt][nt][q] = 0.f;

    // EN prefetch: 36864 B per tile, 256 threads x 16 B x 9
    auto enpf = [&](int h, int buf) {
        const char* sH = (const char*)g_ENhi + (long)h * ENTILE_B + tid * 16;
        const char* sL = (const char*)g_ENlo + (long)h * ENTILE_B + tid * 16;
        uint32_t dH = sb + (buf ? OFF_ENH1 : OFF_ENH0) + tid * 16;
        uint32_t dL = sb + (buf ? OFF_ENL1 : OFF_ENL0) + tid * 16;
#pragma unroll
        for (int k = 0; k < 9; k++) {
            CP16(dH + k * 4096, sH + (long)k * 4096);
            CP16(dL + k * 4096, sL + (long)k * 4096);
        }
    };
    enpf(hb, 0);
    CP_COMMIT();

    // Z build assignment: row = tid/2, half = tid&1 (64 cols each)
    const int zrow = tid >> 1, zhalf = tid & 1;
    const bool evalid = (e0 + zrow) < Ec;
    const float* ep  = g_emb + ((long)b * Ec + e0 + zrow) * Hc + zhalf * 64;
    const float* evp = ev    + ((long)b * Ec + e0 + zrow) * Hc + hb;
    const uint32_t zst = sb + OFF_ZHI + (uint32_t)zrow * 288u + (uint32_t)zhalf * 128u;

    for (int ih = 0; ih < 32; ih++) {
        const int cur = ih & 1;
        CP_WAIT0();                           // EN[cur] copies done (this thread)
        if (ih + 1 < 32) { enpf(hb + ih + 1, cur ^ 1); CP_COMMIT(); }

        // Build Z hi/lo for this h
        const float evv = evalid ? __ldg(evp + ih) : 0.f;
#pragma unroll
        for (int g = 0; g < 8; g++) {
            float4 v0 = evalid ? *reinterpret_cast<const float4*>(ep + g * 8)
                               : make_float4(0.f, 0.f, 0.f, 0.f);
            float4 v1 = evalid ? *reinterpret_cast<const float4*>(ep + g * 8 + 4)
                               : make_float4(0.f, 0.f, 0.f, 0.f);
            float z[8] = {evv * v0.x, evv * v0.y, evv * v0.z, evv * v0.w,
                          evv * v1.x, evv * v1.y, evv * v1.z, evv * v1.w};
            uint32_t hp[4], lp[4];
#pragma unroll
            for (int p = 0; p < 4; p++) {
                __nv_bfloat162 h2 = __floats2bfloat162_rn(z[p * 2], z[p * 2 + 1]);
                float r0 = z[p * 2]     - __low2float(h2);
                float r1 = z[p * 2 + 1] - __high2float(h2);
                __nv_bfloat162 l2 = __floats2bfloat162_rn(r0, r1);
                hp[p] = *reinterpret_cast<uint32_t*>(&h2);
                lp[p] = *reinterpret_cast<uint32_t*>(&l2);
            }
            asm volatile("st.shared.v4.b32 [%0], {%1,%2,%3,%4};"
                         :: "r"(zst + g * 16), "r"(hp[0]), "r"(hp[1]), "r"(hp[2]), "r"(hp[3]));
            asm volatile("st.shared.v4.b32 [%0], {%1,%2,%3,%4};"
                         :: "r"(zst + 36864 + g * 16), "r"(lp[0]), "r"(lp[1]), "r"(lp[2]), "r"(lp[3]));
        }
        __syncthreads();    // Z visible + everyone's cp.async EN[cur] visible

        const uint32_t zhiA = sb + OFF_ZHI + aoff;
        const uint32_t zloA = zhiA + 36864;
        const uint32_t bhB  = sb + (cur ? OFF_ENH1 : OFF_ENH0) + boff;
        const uint32_t blB  = bhB + 36864;

#pragma unroll
        for (int kst = 0; kst < 8; kst++) {
            const uint32_t ka = (uint32_t)kst * 32u;
            uint32_t ah[2][4], al[2][4];
            LDSM_X4(ah[0], zhiA + ka);
            LDSM_X4(ah[1], zhiA + ka + 16u * 288u);
            LDSM_X4(al[0], zloA + ka);
            LDSM_X4(al[1], zloA + ka + 16u * 288u);

            uint32_t bh[8][2], bl[8][2];
#pragma unroll
            for (int p = 0; p < 4; p++) {
                uint32_t r[4];
                LDSM_X4(r, bhB + ka + (uint32_t)p * 16u * 288u);
                bh[2 * p][0] = r[0]; bh[2 * p][1] = r[1];
                bh[2 * p + 1][0] = r[2]; bh[2 * p + 1][1] = r[3];
                LDSM_X4(r, blB + ka + (uint32_t)p * 16u * 288u);
                bl[2 * p][0] = r[0]; bl[2 * p][1] = r[1];
                bl[2 * p + 1][0] = r[2]; bl[2 * p + 1][1] = r[3];
            }
#pragma unroll
            for (int mt = 0; mt < 2; mt++)
#pragma unroll
                for (int nt = 0; nt < 8; nt++) {
                    MMA16816(d[mt][nt], ah[mt], bh[nt]);
                    MMA16816(d[mt][nt], ah[mt], bl[nt]);
                    MMA16816(d[mt][nt], al[mt], bh[nt]);
                }
        }
        __syncthreads();    // MMA reads done before Z/EN buffers are overwritten
    }

    // Epilogue: d[mt][nt] -> g_part[hchunk] partial
    float* dst = g_part + ((long)blockIdx.y * Bc + b) * Ec * Hc;
#pragma unroll
    for (int mt = 0; mt < 2; mt++) {
        const int r0 = e0 + wm * 32 + mt * 16 + (lane >> 2);
        const int r1 = r0 + 8;
#pragma unroll
        for (int nt = 0; nt < 8; nt++) {
            const int col = wn * 64 + nt * 8 + (lane & 3) * 2;
            if (r0 < Ec)
                *reinterpret_cast<float2*>(dst + (long)r0 * Hc + col) =
                    make_float2(d[mt][nt][0], d[mt][nt][1]);
            if (r1 < Ec)
                *reinterpret_cast<float2*>(dst + (long)r1 * Hc + col) =
                    make_float2(d[mt][nt][2], d[mt][nt][3]);
        }
    }
}

// Reduce h-chunk partials into g_new
__global__ __launch_bounds__(256) void k_reduce_new() {
    int idx = blockIdx.x * blockDim.x + threadIdx.x;
    const int total = Bc * Ec * Hc / 4;
    if (idx >= total) return;
    float4 a = reinterpret_cast<const float4*>(g_part)[idx];
#pragma unroll
    for (int s = 1; s < HCH; s++) {
        float4 v = reinterpret_cast<const float4*>(g_part + (long)s * Bc * Ec * Hc)[idx];
        a.x += v.x; a.y += v.y; a.z += v.z; a.w += v.w;
    }
    reinterpret_cast<float4*>(g_new)[idx] = a;
}

// ---------------------------------------------------------------------------
// Stage 4 (split-K, fp32 FFMA) + final reduce
// ---------------------------------------------------------------------------
__global__ __launch_bounds__(256) void k_agg_part(const float* __restrict__ e2n) {
    const int b  = blockIdx.z;
    const int s  = blockIdx.y;
    const int n0 = blockIdx.x * 128;
    const int kbeg = s * (Ec / S4);
    const int kend = kbeg + (Ec / S4);
    const float* A  = e2n   + (long)b * Nc * Ec;
    const float* Bm = g_new + (long)b * Ec * Hc;

    __shared__ float As[8][129];
    __shared__ float Bs[8][128];
    __shared__ float rs2[128][2];

    const int tid = threadIdx.x;
    const int tx = tid & 15, ty = tid >> 4;
    const int lr = tid >> 1;
    const int half = tid & 1;
    const int lk = half * 4;

    float acc[8][8];
#pragma unroll
    for (int r = 0; r < 8; r++)
#pragma unroll
        for (int c = 0; c < 8; c++) acc[r][c] = 0.f;
    float rs = 0.f;

    for (int k0 = kbeg; k0 < kend; k0 += 8) {
        float4 av = make_float4(0.f, 0.f, 0.f, 0.f);
        if (n0 + lr < Nc)
            av = *reinterpret_cast<const float4*>(&A[(long)(n0 + lr) * Ec + k0 + lk]);
        As[lk + 0][lr] = av.x; As[lk + 1][lr] = av.y;
        As[lk + 2][lr] = av.z; As[lk + 3][lr] = av.w;
        rs += av.x + av.y + av.z + av.w;

        const int bk = tid >> 5;
        const int bc = (tid & 31) * 4;
        float4 bv = *reinterpret_cast<const float4*>(&Bm[(long)(k0 + bk) * Hc + bc]);
        *reinterpret_cast<float4*>(&Bs[bk][bc]) = bv;
        __syncthreads();

#pragma unroll
        for (int kk = 0; kk < 8; kk++) {
            float a[8], bb[8];
#pragma unroll
            for (int r = 0; r < 8; r++) a[r]  = As[kk][ty + r * 16];
#pragma unroll
            for (int c = 0; c < 8; c++) bb[c] = Bs[kk][tx + c * 16];
#pragma unroll
            for (int r = 0; r < 8; r++)
#pragma unroll
                for (int c = 0; c < 8; c++) acc[r][c] += a[r] * bb[c];
        }
        __syncthreads();
    }

    rs2[lr][half] = rs;
    __syncthreads();
    if (tid < 128 && n0 + tid < Nc)
        g_normp[s][(long)b * Nc + n0 + tid] = rs2[tid][0] + rs2[tid][1];

    float* C = g_part + ((long)s * Bc + b) * Nc * Hc;
#pragma unroll
    for (int r = 0; r < 8; r++) {
        int n = n0 + ty + r * 16;
        if (n < Nc) {
#pragma unroll
            for (int c = 0; c < 8; c++) C[(long)n * Hc + tx + c * 16] = acc[r][c];
        }
    }
}

__global__ __launch_bounds__(256) void k_reduce_agg(const float* __restrict__ ns,
                                                    float* __restrict__ out) {
    int idx = blockIdx.x * blockDim.x + threadIdx.x;
    const int total = Bc * Nc * Hc / 4;
    if (idx >= total) return;
    const int row = (idx * 4) / Hc;
    float nm = 1.0f;
#pragma unroll
    for (int s = 0; s < S4; s++) nm += g_normp[s][row];

    float4 a = reinterpret_cast<const float4*>(g_part)[idx];
#pragma unroll
    for (int s = 1; s < S4; s++) {
        float4 v = reinterpret_cast<const float4*>(g_part + (long)s * Bc * Nc * Hc)[idx];
        a.x += v.x; a.y += v.y; a.z += v.z; a.w += v.w;
    }
    float4 nv = reinterpret_cast<const float4*>(ns)[idx];
    float inv = 1.0f / nm;
    a.x = (a.x + nv.x) * inv; a.y = (a.y + nv.y) * inv;
    a.z = (a.z + nv.z) * inv; a.w = (a.w + nv.w) * inv;
    reinterpret_cast<float4*>(out)[idx] = a;
}

// ---------------------------------------------------------------------------
extern "C" void kernel_launch(void* const* d_in, const int* in_sizes, int n_in,
                              void* d_out, int out_size) {
    const float* node_state   = (const float*)d_in[0];   // [B,N,H]
    const float* edge_vec     = (const float*)d_in[1];   // [B,E,H]
    const float* node2edge    = (const float*)d_in[2];   // [B,E,N]
    const float* edge2node    = (const float*)d_in[3];   // [B,N,E]
    const float* edge_network = (const float*)d_in[4];   // [H,H,H]
    float* out = (float*)d_out;

    // Idempotent; safe under graph capture; no static guards.
    cudaFuncSetAttribute(k_edgeconv_mma, cudaFuncAttributeMaxDynamicSharedMemorySize,
                         SMEM3_TOTAL);

    dim3 g1(128, 128);
    k_split_en<<<g1, Hc>>>(edge_network);

    dim3 g2((Ec + 127) / 128, S2, Bc);
    k_gemm_n2e_part<<<g2, 256>>>(node2edge, node_state);

    int tot2 = Bc * Ec * Hc / 4;
    k_reduce_emb<<<(tot2 + 255) / 256, 256>>>();

    dim3 g3((Ec + 127) / 128, HCH, Bc);
    k_edgeconv_mma<<<g3, 256, SMEM3_TOTAL>>>(edge_vec);

    k_reduce_new<<<(tot2 + 255) / 256, 256>>>();

    dim3 g4((Nc + 127) / 128, S4, Bc);
    k_agg_part<<<g4, 256>>>(edge2node);

    int tot4 = Bc * Nc * Hc / 4;
    k_reduce_agg<<<(tot4 + 255) / 256, 256>>>(node_state, out);
}

// round 14
// speedup vs baseline: 3.9696x; 1.4457x over previous
#include <cuda_runtime.h>
#include <cuda_bf16.h>
#include <cstdint>

#define Bc 2
#define Nc 1000
#define Ec 2000
#define Hc 128
#define S2 5      // split-K for stage 2 (N=1000 -> 5 x 200)
#define S4 10     // split-K for stage 4 (E=2000 -> 10 x 200)
#define HCH 2     // stage-3 h-chunks (2 x 64)

#define ENP   136                      // bf16 elems per padded row (272 B)
#define ENPB  272
#define ENT_B (128 * ENPB)             // 34816 B per h tile (hi or lo)

// ---------------------------------------------------------------------------
// Scratch (no allocations). g_part time-shared across disjoint stage lifetimes.
// ---------------------------------------------------------------------------
__device__ float         g_emb [Bc * Ec * Hc];
__device__ float         g_new [Bc * Ec * Hc];
__device__ float         g_part[S2 * Bc * Ec * Hc];       // 10.24 MB
__device__ float         g_normp[S4][Bc * Nc];
__device__ __nv_bfloat16 g_ENhi[128 * 128 * ENP];         // [h][i][j] pitch 272B
__device__ __nv_bfloat16 g_ENlo[128 * 128 * ENP];

// ---------------------------------------------------------------------------
// PTX helpers (sm_80-era: valid for plain sm_103 target)
// ---------------------------------------------------------------------------
#define CP16(dst, src) \
    asm volatile("cp.async.cg.shared.global [%0], [%1], 16;" :: "r"(dst), "l"(src))
#define CP_COMMIT() asm volatile("cp.async.commit_group;")
#define CP_WAIT0()  asm volatile("cp.async.wait_group 0;" ::: "memory")

#define LDSM_X4(r, addr) \
    asm volatile("ldmatrix.sync.aligned.m8n8.x4.shared.b16 {%0,%1,%2,%3}, [%4];" \
                 : "=r"((r)[0]), "=r"((r)[1]), "=r"((r)[2]), "=r"((r)[3]) : "r"(addr))

#define MMA16816(d, a, b) \
    asm volatile("mma.sync.aligned.m16n8k16.row.col.f32.bf16.bf16.f32 " \
                 "{%0,%1,%2,%3}, {%4,%5,%6,%7}, {%8,%9}, {%0,%1,%2,%3};" \
                 : "+f"((d)[0]), "+f"((d)[1]), "+f"((d)[2]), "+f"((d)[3]) \
                 : "r"((a)[0]), "r"((a)[1]), "r"((a)[2]), "r"((a)[3]), \
                   "r"((b)[0]), "r"((b)[1]))

// SMEM layout for stage-3 kernel
#define OFF_ENH0  0
#define OFF_ENL0  34816
#define OFF_ENH1  69632
#define OFF_ENL1  104448
#define OFF_EV    139264                  // 64 h x pitch-65 floats = 16640 B
#define SMEM3_TOTAL (OFF_EV + 64 * 65 * 4)

// ---------------------------------------------------------------------------
// Stage 1: split EN[h][i][j] fp32 -> bf16 hi/lo, pitch-272 row-major per-h tiles
// ---------------------------------------------------------------------------
__global__ void k_split_en(const float* __restrict__ EN) {
    int j = threadIdx.x, h = blockIdx.x, i = blockIdx.y;
    float x = EN[((long)h * Hc + i) * Hc + j];
    __nv_bfloat16 hi = __float2bfloat16(x);
    __nv_bfloat16 lo = __float2bfloat16(x - __bfloat162float(hi));
    long off = ((long)h * 128 + i) * ENP + j;
    g_ENhi[off] = hi;
    g_ENlo[off] = lo;
}

// ---------------------------------------------------------------------------
// Stage 2 (split-K, fp32 FFMA)
// ---------------------------------------------------------------------------
__global__ __launch_bounds__(256) void k_gemm_n2e_part(const float* __restrict__ n2e,
                                                       const float* __restrict__ ns) {
    const int b  = blockIdx.z;
    const int s  = blockIdx.y;
    const int e0 = blockIdx.x * 128;
    const int kbeg = s * (Nc / S2);
    const int kend = kbeg + (Nc / S2);
    const float* A  = n2e + (long)b * Ec * Nc;
    const float* Bm = ns  + (long)b * Nc * Hc;
    __shared__ float As[8][129];
    __shared__ float Bs[8][128];

    const int tid = threadIdx.x;
    const int tx = tid & 15, ty = tid >> 4;
    const int lr = tid >> 1;
    const int lk = (tid & 1) * 4;

    float acc[8][8];
#pragma unroll
    for (int r = 0; r < 8; r++)
#pragma unroll
        for (int c = 0; c < 8; c++) acc[r][c] = 0.f;

    for (int k0 = kbeg; k0 < kend; k0 += 8) {
        float4 av = make_float4(0.f, 0.f, 0.f, 0.f);
        if (e0 + lr < Ec)
            av = *reinterpret_cast<const float4*>(&A[(long)(e0 + lr) * Nc + k0 + lk]);
        As[lk + 0][lr] = av.x; As[lk + 1][lr] = av.y;
        As[lk + 2][lr] = av.z; As[lk + 3][lr] = av.w;

        const int bk = tid >> 5;
        const int bc = (tid & 31) * 4;
        float4 bv = *reinterpret_cast<const float4*>(&Bm[(long)(k0 + bk) * Hc + bc]);
        *reinterpret_cast<float4*>(&Bs[bk][bc]) = bv;
        __syncthreads();

#pragma unroll
        for (int kk = 0; kk < 8; kk++) {
            float a[8], bb[8];
#pragma unroll
            for (int r = 0; r < 8; r++) a[r]  = As[kk][ty + r * 16];
#pragma unroll
            for (int c = 0; c < 8; c++) bb[c] = Bs[kk][tx + c * 16];
#pragma unroll
            for (int r = 0; r < 8; r++)
#pragma unroll
                for (int c = 0; c < 8; c++) acc[r][c] += a[r] * bb[c];
        }
        __syncthreads();
    }

    float* C = g_part + ((long)s * Bc + b) * Ec * Hc;
#pragma unroll
    for (int r = 0; r < 8; r++) {
        int e = e0 + ty + r * 16;
        if (e < Ec) {
#pragma unroll
            for (int c = 0; c < 8; c++) C[(long)e * Hc + tx + c * 16] = acc[r][c];
        }
    }
}

__global__ __launch_bounds__(256) void k_reduce_emb() {
    int idx = blockIdx.x * blockDim.x + threadIdx.x;
    const int total = Bc * Ec * Hc / 4;
    if (idx >= total) return;
    float4 a = reinterpret_cast<const float4*>(g_part)[idx];
#pragma unroll
    for (int s = 1; s < S2; s++) {
        float4 v = reinterpret_cast<const float4*>(g_part + (long)s * Bc * Ec * Hc)[idx];
        a.x += v.x; a.y += v.y; a.z += v.z; a.w += v.w;
    }
    reinterpret_cast<float4*>(g_emb)[idx] = a;
}

// ---------------------------------------------------------------------------
// Stage 3 v2 (mma.sync bf16x3, constant-A): per CTA (64 e-rows, 64-h chunk, b):
//   A = emb[e,j] hi/lo — ldmatrix'd into REGISTERS once (constant across h).
//   per h: G[e,i] = A @ EN_h^T (3 passes), then D += ev[e,h] * G  (fp32).
// No per-h A traffic; EN pitch 272B -> conflict-free ldmatrix.
// 8 warps: wm=wid&3 (rows wm*16), wn=wid>>2 (cols wn*64). nt=8 (8-col tiles).
// ---------------------------------------------------------------------------
__global__ __launch_bounds__(256, 1)
void k_edgeconv_mma(const float* __restrict__ ev) {
    extern __shared__ char smem[];
    const uint32_t sb = (uint32_t)__cvta_generic_to_shared(smem);
    const int e0 = blockIdx.x * 64;
    const int hb = blockIdx.y * 64;
    const int b  = blockIdx.z;
    const int tid = threadIdx.x;
    const int lane = tid & 31, wid = tid >> 5;
    const int wm = wid & 3, wn = wid >> 2;

    float* evs = reinterpret_cast<float*>(smem + OFF_EV);   // [h][e] pitch 65

    // ---- stage emb hi/lo (64 rows x 128 j) into ENH0/ENL0 region ----
    for (int idx = tid; idx < 64 * 64; idx += 256) {        // j-pairs
        int r = idx >> 6, jp = idx & 63;
        float2 v = make_float2(0.f, 0.f);
        if (e0 + r < Ec)
            v = *reinterpret_cast<const float2*>(
                    g_emb + ((long)b * Ec + e0 + r) * Hc + jp * 2);
        __nv_bfloat162 h2 = __floats2bfloat162_rn(v.x, v.y);
        __nv_bfloat162 l2 = __floats2bfloat162_rn(v.x - __low2float(h2),
                                                  v.y - __high2float(h2));
        uint32_t hu = *reinterpret_cast<uint32_t*>(&h2);
        uint32_t lu = *reinterpret_cast<uint32_t*>(&l2);
        uint32_t addr = (uint32_t)r * ENPB + (uint32_t)jp * 4;
        asm volatile("st.shared.b32 [%0], %1;" :: "r"(sb + OFF_ENH0 + addr), "r"(hu));
        asm volatile("st.shared.b32 [%0], %1;" :: "r"(sb + OFF_ENL0 + addr), "r"(lu));
    }
    // ---- stage ev transposed [h][e] (pitch 65 -> conflict-free) ----
    for (int idx = tid; idx < 64 * 64; idx += 256) {
        int e = idx >> 6, h = idx & 63;
        float v = 0.f;
        if (e0 + e < Ec)
            v = ev[((long)b * Ec + e0 + e) * Hc + hb + h];
        evs[h * 65 + e] = v;
    }
    __syncthreads();

    // ---- load constant A fragments into registers ----
    uint32_t ahi[8][4], alo[8][4];
    const uint32_t aoff = (uint32_t)(wm * 16 + (lane & 15)) * ENPB
                        + (uint32_t)(lane >> 4) * 16u;
#pragma unroll
    for (int kst = 0; kst < 8; kst++) {
        LDSM_X4(ahi[kst], sb + OFF_ENH0 + aoff + kst * 32);
        LDSM_X4(alo[kst], sb + OFF_ENL0 + aoff + kst * 32);
    }
    __syncthreads();   // staging area free -> becomes EN buffer 0

    // B ldmatrix per-lane base offset (within an EN tile)
    const uint32_t boff = (uint32_t)(wn * 64 + (lane & 7) + ((lane >> 4) & 1) * 8) * ENPB
                        + (uint32_t)((lane >> 3) & 1) * 16u;

    float d[8][4];
#pragma unroll
    for (int nt = 0; nt < 8; nt++)
#pragma unroll
        for (int q = 0; q < 4; q++) d[nt][q] = 0.f;

    // EN prefetch: hi tile 2176 x 16B chunks (8 full rounds + 128 tail), same lo
    auto enpf = [&](int h, int buf) {
        const char* sH = (const char*)g_ENhi + (long)h * ENT_B;
        const char* sL = (const char*)g_ENlo + (long)h * ENT_B;
        uint32_t dH = sb + (buf ? OFF_ENH1 : OFF_ENH0);
        uint32_t dL = sb + (buf ? OFF_ENL1 : OFF_ENL0);
#pragma unroll
        for (int k = 0; k < 8; k++) {
            uint32_t o = (uint32_t)(k * 256 + tid) * 16u;
            CP16(dH + o, sH + o);
            CP16(dL + o, sL + o);
        }
        if (tid < 128) {
            uint32_t o = (uint32_t)(2048 + tid) * 16u;
            CP16(dH + o, sH + o);
            CP16(dL + o, sL + o);
        }
    };
    enpf(hb, 0);
    CP_COMMIT();

    const int evr0 = wm * 16 + (lane >> 2);
    for (int ih = 0; ih < 64; ih++) {
        const int cur = ih & 1;
        CP_WAIT0();
        __syncthreads();   // all EN[cur] chunks visible; prior-h MMAs complete
        if (ih + 1 < 64) { enpf(hb + ih + 1, cur ^ 1); CP_COMMIT(); }

        const uint32_t bhB = sb + (cur ? OFF_ENH1 : OFF_ENH0) + boff;
        const uint32_t blB = bhB + (OFF_ENL0 - OFF_ENH0);

        float g[8][4];
#pragma unroll
        for (int nt = 0; nt < 8; nt++)
#pragma unroll
            for (int q = 0; q < 4; q++) g[nt][q] = 0.f;

#pragma unroll
        for (int kst = 0; kst < 8; kst++) {
            const uint32_t ka = (uint32_t)kst * 32u;
            uint32_t bh[8][2], bl[8][2];
#pragma unroll
            for (int p = 0; p < 4; p++) {
                uint32_t r[4];
                LDSM_X4(r, bhB + ka + (uint32_t)p * 16u * ENPB);
                bh[2 * p][0] = r[0]; bh[2 * p][1] = r[1];
                bh[2 * p + 1][0] = r[2]; bh[2 * p + 1][1] = r[3];
                LDSM_X4(r, blB + ka + (uint32_t)p * 16u * ENPB);
                bl[2 * p][0] = r[0]; bl[2 * p][1] = r[1];
                bl[2 * p + 1][0] = r[2]; bl[2 * p + 1][1] = r[3];
            }
#pragma unroll
            for (int nt = 0; nt < 8; nt++) {
                MMA16816(g[nt], ahi[kst], bh[nt]);
                MMA16816(g[nt], ahi[kst], bl[nt]);
                MMA16816(g[nt], alo[kst], bh[nt]);
            }
        }

        // epilogue: D += ev[e,h] * G (fp32; c0,c1 -> row r0, c2,c3 -> row r0+8)
        const float ev0 = evs[ih * 65 + evr0];
        const float ev1 = evs[ih * 65 + evr0 + 8];
#pragma unroll
        for (int nt = 0; nt < 8; nt++) {
            d[nt][0] += ev0 * g[nt][0];
            d[nt][1] += ev0 * g[nt][1];
            d[nt][2] += ev1 * g[nt][2];
            d[nt][3] += ev1 * g[nt][3];
        }
    }

    // store h-chunk partial
    float* dst = g_part + ((long)blockIdx.y * Bc + b) * Ec * Hc;
    const int r0 = e0 + wm * 16 + (lane >> 2);
    const int r1 = r0 + 8;
#pragma unroll
    for (int nt = 0; nt < 8; nt++) {
        const int col = wn * 64 + nt * 8 + (lane & 3) * 2;
        if (r0 < Ec)
            *reinterpret_cast<float2*>(dst + (long)r0 * Hc + col) =
                make_float2(d[nt][0], d[nt][1]);
        if (r1 < Ec)
            *reinterpret_cast<float2*>(dst + (long)r1 * Hc + col) =
                make_float2(d[nt][2], d[nt][3]);
    }
}

// Reduce h-chunk partials into g_new
__global__ __launch_bounds__(256) void k_reduce_new() {
    int idx = blockIdx.x * blockDim.x + threadIdx.x;
    const int total = Bc * Ec * Hc / 4;
    if (idx >= total) return;
    float4 a = reinterpret_cast<const float4*>(g_part)[idx];
#pragma unroll
    for (int s = 1; s < HCH; s++) {
        float4 v = reinterpret_cast<const float4*>(g_part + (long)s * Bc * Ec * Hc)[idx];
        a.x += v.x; a.y += v.y; a.z += v.z; a.w += v.w;
    }
    reinterpret_cast<float4*>(g_new)[idx] = a;
}

// ---------------------------------------------------------------------------
// Stage 4 (split-K, fp32 FFMA) + final reduce
// ---------------------------------------------------------------------------
__global__ __launch_bounds__(256) void k_agg_part(const float* __restrict__ e2n) {
    const int b  = blockIdx.z;
    const int s  = blockIdx.y;
    const int n0 = blockIdx.x * 128;
    const int kbeg = s * (Ec / S4);
    const int kend = kbeg + (Ec / S4);
    const float* A  = e2n   + (long)b * Nc * Ec;
    const float* Bm = g_new + (long)b * Ec * Hc;

    __shared__ float As[8][129];
    __shared__ float Bs[8][128];
    __shared__ float rs2[128][2];

    const int tid = threadIdx.x;
    const int tx = tid & 15, ty = tid >> 4;
    const int lr = tid >> 1;
    const int half = tid & 1;
    const int lk = half * 4;

    float acc[8][8];
#pragma unroll
    for (int r = 0; r < 8; r++)
#pragma unroll
        for (int c = 0; c < 8; c++) acc[r][c] = 0.f;
    float rs = 0.f;

    for (int k0 = kbeg; k0 < kend; k0 += 8) {
        float4 av = make_float4(0.f, 0.f, 0.f, 0.f);
        if (n0 + lr < Nc)
            av = *reinterpret_cast<const float4*>(&A[(long)(n0 + lr) * Ec + k0 + lk]);
        As[lk + 0][lr] = av.x; As[lk + 1][lr] = av.y;
        As[lk + 2][lr] = av.z; As[lk + 3][lr] = av.w;
        rs += av.x + av.y + av.z + av.w;

        const int bk = tid >> 5;
        const int bc = (tid & 31) * 4;
        float4 bv = *reinterpret_cast<const float4*>(&Bm[(long)(k0 + bk) * Hc + bc]);
        *reinterpret_cast<float4*>(&Bs[bk][bc]) = bv;
        __syncthreads();

#pragma unroll
        for (int kk = 0; kk < 8; kk++) {
            float a[8], bb[8];
#pragma unroll
            for (int r = 0; r < 8; r++) a[r]  = As[kk][ty + r * 16];
#pragma unroll
            for (int c = 0; c < 8; c++) bb[c] = Bs[kk][tx + c * 16];
#pragma unroll
            for (int r = 0; r < 8; r++)
#pragma unroll
                for (int c = 0; c < 8; c++) acc[r][c] += a[r] * bb[c];
        }
        __syncthreads();
    }

    rs2[lr][half] = rs;
    __syncthreads();
    if (tid < 128 && n0 + tid < Nc)
        g_normp[s][(long)b * Nc + n0 + tid] = rs2[tid][0] + rs2[tid][1];

    float* C = g_part + ((long)s * Bc + b) * Nc * Hc;
#pragma unroll
    for (int r = 0; r < 8; r++) {
        int n = n0 + ty + r * 16;
        if (n < Nc) {
#pragma unroll
            for (int c = 0; c < 8; c++) C[(long)n * Hc + tx + c * 16] = acc[r][c];
        }
    }
}

__global__ __launch_bounds__(256) void k_reduce_agg(const float* __restrict__ ns,
                                                    float* __restrict__ out) {
    int idx = blockIdx.x * blockDim.x + threadIdx.x;
    const int total = Bc * Nc * Hc / 4;
    if (idx >= total) return;
    const int row = (idx * 4) / Hc;
    float nm = 1.0f;
#pragma unroll
    for (int s = 0; s < S4; s++) nm += g_normp[s][row];

    float4 a = reinterpret_cast<const float4*>(g_part)[idx];
#pragma unroll
    for (int s = 1; s < S4; s++) {
        float4 v = reinterpret_cast<const float4*>(g_part + (long)s * Bc * Nc * Hc)[idx];
        a.x += v.x; a.y += v.y; a.z += v.z; a.w += v.w;
    }
    float4 nv = reinterpret_cast<const float4*>(ns)[idx];
    float inv = 1.0f / nm;
    a.x = (a.x + nv.x) * inv; a.y = (a.y + nv.y) * inv;
    a.z = (a.z + nv.z) * inv; a.w = (a.w + nv.w) * inv;
    reinterpret_cast<float4*>(out)[idx] = a;
}

// ---------------------------------------------------------------------------
extern "C" void kernel_launch(void* const* d_in, const int* in_sizes, int n_in,
                              void* d_out, int out_size) {
    const float* node_state   = (const float*)d_in[0];   // [B,N,H]
    const float* edge_vec     = (const float*)d_in[1];   // [B,E,H]
    const float* node2edge    = (const float*)d_in[2];   // [B,E,N]
    const float* edge2node    = (const float*)d_in[3];   // [B,N,E]
    const float* edge_network = (const float*)d_in[4];   // [H,H,H]
    float* out = (float*)d_out;

    // Idempotent; safe under graph capture; no static guards.
    cudaFuncSetAttribute(k_edgeconv_mma, cudaFuncAttributeMaxDynamicSharedMemorySize,
                         SMEM3_TOTAL);

    dim3 g1(128, 128);
    k_split_en<<<g1, Hc>>>(edge_network);

    dim3 g2((Ec + 127) / 128, S2, Bc);
    k_gemm_n2e_part<<<g2, 256>>>(node2edge, node_state);

    int tot2 = Bc * Ec * Hc / 4;
    k_reduce_emb<<<(tot2 + 255) / 256, 256>>>();

    dim3 g3((Ec + 63) / 64, HCH, Bc);
    k_edgeconv_mma<<<g3, 256, SMEM3_TOTAL>>>(edge_vec);

    k_reduce_new<<<(tot2 + 255) / 256, 256>>>();

    dim3 g4((Nc + 127) / 128, S4, Bc);
    k_agg_part<<<g4, 256>>>(edge2node);

    int tot4 = Bc * Nc * Hc / 4;
    k_reduce_agg<<<(tot4 + 255) / 256, 256>>>(node_state, out);
}